// round 12
// baseline (speedup 1.0000x reference)
#include <cuda_runtime.h>
#include <cuda_fp16.h>
#include <cstdint>
#include <math.h>

#define NTOK 16384
#define DIM  1024
#define NE   8
#define CAP  2560          // int(1.25 * 16384 / 8)
#define BK   64
#define NCH  (DIM / BK)    // 16
#define PITCH 144          // 64 fp16 = 128B + 16B pad (conflict-free phases)
#define BH_OFF  36864      // 256*144 (A tile)
#define STAGE_B 55296      // A 36864 + B 18432
#define SMEM_DYN (1024 + 3 * STAGE_B)   // 166912
#define TILES_PER_E 80     // 10 m-tiles x 8 n-tiles
#define G1_ITEMS (NE * TILES_PER_E)     // 640
#define TOTAL_ITEMS (2 * G1_ITEMS)      // 1280
#define GRID_PERSIST 152
#define RBLK 512           // router blocks in prep kernel (32 tokens each)
#define WN4  (NE * DIM * DIM / 4)       // float4 count per W tensor
#define WBLK (2 * WN4 / 256)            // 16384 convert blocks

// ---------------- device scratch (no allocation allowed) -------------------
__device__ int      g_top[NTOK * 2];
__device__ float    g_gate[NTOK * 2];
__device__ int      g_slot[NTOK * 2];
__device__ int      g_row_token[NE * CAP];
__device__ float    g_row_gate[NE * CAP];
__device__ int      g_load[NE];
__device__ int      g_next;                            // work-queue cursor
__device__ int      g_done[NE];                        // gemm1 tiles done / expert
__device__ uint16_t g_xh[(size_t)NTOK * DIM];          // x as fp16
__device__ uint16_t g_w1h[(size_t)NE * DIM * DIM];     // W1 as fp16
__device__ uint16_t g_w2h[(size_t)NE * DIM * DIM];     // W2 as fp16
__device__ uint16_t g_Hh[(size_t)NE * CAP * DIM];      // hidden as fp16
__device__ uint16_t g_Oh[(size_t)NE * CAP * DIM];      // gated expert out, fp16

// ---------------- helpers ---------------------------------------------------
__device__ __forceinline__ uint32_t smem_u32(const void* p) {
    uint32_t a;
    asm("{ .reg .u64 t; cvta.to.shared.u64 t, %1; cvt.u32.u64 %0, t; }"
        : "=r"(a) : "l"(p));
    return a;
}
__device__ __forceinline__ void cpa16(uint32_t dst, const void* src) {
    asm volatile("cp.async.cg.shared.global [%0], [%1], 16;"
                 :: "r"(dst), "l"(src));
}
#define CP_COMMIT() asm volatile("cp.async.commit_group;" ::: "memory")
#define CP_WAIT1()  asm volatile("cp.async.wait_group 1;" ::: "memory")

__device__ __forceinline__ void ldsm4(uint32_t* r, uint32_t addr) {
    asm volatile("ldmatrix.sync.aligned.m8n8.x4.shared.b16 {%0,%1,%2,%3}, [%4];"
                 : "=r"(r[0]), "=r"(r[1]), "=r"(r[2]), "=r"(r[3]) : "r"(addr));
}
__device__ __forceinline__ void mma_f16(float* d, const uint32_t* a,
                                        const uint32_t* b) {
    asm volatile(
        "mma.sync.aligned.m16n8k16.row.col.f32.f16.f16.f32 "
        "{%0,%1,%2,%3}, {%4,%5,%6,%7}, {%8,%9}, {%0,%1,%2,%3};"
        : "+f"(d[0]), "+f"(d[1]), "+f"(d[2]), "+f"(d[3])
        : "r"(a[0]), "r"(a[1]), "r"(a[2]), "r"(a[3]), "r"(b[0]), "r"(b[1]));
}
__device__ __forceinline__ uint32_t cvt2h(float a, float b) {
    __half2 h = __floats2half2_rn(a, b);
    return *(uint32_t*)&h;
}
__device__ __forceinline__ int ld_acq(const int* p) {
    int v;
    asm volatile("ld.acquire.gpu.global.b32 %0, [%1];" : "=r"(v) : "l"(p));
    return v;
}

// ---------------- prep: W1/W2 -> fp16 AND router + x -> fp16 (one launch) --
__global__ void __launch_bounds__(256)
prep_kernel(const float* __restrict__ x,  const float* __restrict__ Wr,
            const float* __restrict__ br, const float* __restrict__ W1,
            const float* __restrict__ W2) {
    const int tid = threadIdx.x;
    if (blockIdx.x >= RBLK) {
        // ---- weight conversion: one float4 per thread ----
        int i = (blockIdx.x - RBLK) * 256 + tid;
        const float4* src;
        uint2* dst;
        if (i < WN4) { src = (const float4*)W1; dst = (uint2*)g_w1h; }
        else         { src = (const float4*)W2; dst = (uint2*)g_w2h; i -= WN4; }
        float4 v = __ldg(src + i);
        dst[i] = make_uint2(cvt2h(v.x, v.y), cvt2h(v.z, v.w));
        return;
    }
    // ---- router: 4 tokens per warp (amortize Wr reads 4x) ----
    const int lane = tid & 31, wid = tid >> 5;
    const int tb = (blockIdx.x * 8 + wid) * 4;
    const float4* xr[4];
    uint2* xo[4];
#pragma unroll
    for (int t = 0; t < 4; t++) {
        xr[t] = (const float4*)(x + (size_t)(tb + t) * DIM);
        xo[t] = (uint2*)(g_xh + (size_t)(tb + t) * DIM);
    }
    float acc[4][NE];
#pragma unroll
    for (int t = 0; t < 4; t++)
#pragma unroll
        for (int e = 0; e < NE; e++) acc[t][e] = 0.f;
#pragma unroll
    for (int i = 0; i < 8; i++) {
        const int d4 = lane + i * 32;
        float4 xv[4];
#pragma unroll
        for (int t = 0; t < 4; t++) {
            xv[t] = __ldg(xr[t] + d4);
            xo[t][d4] = make_uint2(cvt2h(xv[t].x, xv[t].y), cvt2h(xv[t].z, xv[t].w));
        }
#pragma unroll
        for (int e = 0; e < NE; e++) {
            const float4 w = __ldg((const float4*)(Wr + e * DIM) + d4);
#pragma unroll
            for (int t = 0; t < 4; t++)
                acc[t][e] += xv[t].x * w.x + xv[t].y * w.y
                           + xv[t].z * w.z + xv[t].w * w.w;
        }
    }
#pragma unroll
    for (int t = 0; t < 4; t++)
#pragma unroll
        for (int e = 0; e < NE; e++)
#pragma unroll
            for (int o = 16; o; o >>= 1)
                acc[t][e] += __shfl_xor_sync(0xffffffffu, acc[t][e], o);
    if (lane == 0) {
#pragma unroll
        for (int t = 0; t < 4; t++) {
            const int token = tb + t;
            float l[NE];
#pragma unroll
            for (int e = 0; e < NE; e++) l[e] = acc[t][e] + br[e];
            float v1 = -3.4e38f; int i1 = 0;
#pragma unroll
            for (int e = 0; e < NE; e++) if (l[e] > v1) { v1 = l[e]; i1 = e; }
            float v2 = -3.4e38f; int i2 = 0;
#pragma unroll
            for (int e = 0; e < NE; e++) if (e != i1 && l[e] > v2) { v2 = l[e]; i2 = e; }
            float ex = expf(v2 - v1);
            float inv = 1.f / (1.f + ex);
            g_top[2 * token]      = i1;
            g_top[2 * token + 1]  = i2;
            g_gate[2 * token]     = inv;
            g_gate[2 * token + 1] = ex * inv;
        }
    }
}

// ---------------- dispatch scan: 16 tokens/thread, one block scan ----------
__global__ void __launch_bounds__(1024)
scan_kernel() {
    const int e = blockIdx.x;
    const int tid = threadIdx.x;
    const int lane = tid & 31, wid = tid >> 5;
    __shared__ int wsum[32];
    __shared__ int stotal;

    const int base = tid * 16;
    unsigned mask = 0, which = 0;
    int cnt = 0;
#pragma unroll
    for (int j = 0; j < 16; j++) {
        const int n = base + j;
        const int t0 = g_top[2 * n], t1 = g_top[2 * n + 1];
        const bool m0 = (t0 == e), m1 = (t1 == e);
        if (m0 | m1) {
            mask |= 1u << j;
            if (!m0) which |= 1u << j;
            cnt++;
        }
    }
    // block-wide exclusive scan of cnt (stable order = thread order)
    int s = cnt;
#pragma unroll
    for (int o = 1; o < 32; o <<= 1) {
        int u = __shfl_up_sync(0xffffffffu, s, o);
        if (lane >= o) s += u;
    }
    if (lane == 31) wsum[wid] = s;
    const int wexcl = s - cnt;
    __syncthreads();
    if (wid == 0) {
        int v = wsum[lane];
        int ss = v;
#pragma unroll
        for (int o = 1; o < 32; o <<= 1) {
            int u = __shfl_up_sync(0xffffffffu, ss, o);
            if (lane >= o) ss += u;
        }
        wsum[lane] = ss - v;
        if (lane == 31) stotal = ss;
    }
    __syncthreads();
    int pos = wsum[wid] + wexcl;
#pragma unroll
    for (int j = 0; j < 16; j++) {
        if (mask & (1u << j)) {
            const int n = base + j;
            const int k = (which >> j) & 1;
            if (pos < CAP) {
                g_row_token[e * CAP + pos] = n;
                g_row_gate[e * CAP + pos]  = g_gate[2 * n + k];
                g_slot[2 * n + k] = pos;
            } else {
                g_slot[2 * n + k] = -1;
            }
            pos++;
        }
    }
    if (tid == 0) g_load[e] = stotal < CAP ? stotal : CAP;
}

// ---------------- fused persistent GEMM (both layers, work queue) ----------
__global__ void __launch_bounds__(256)
moe_gemm_fused(const float* __restrict__ b1, const float* __restrict__ b2) {
    extern __shared__ __align__(16) char dsm[];
    __shared__ int sidx;

    const int tid = threadIdx.x;
    const int lane = tid & 31, wid = tid >> 5;
    const int wm = wid >> 1, wn = wid & 1;     // warp tile 64x64
    const uint32_t sb = smem_u32(dsm);
    const uint32_t st0 = sb + 1024;

    uint32_t aoff[4], boff[4];
#pragma unroll
    for (int ms = 0; ms < 4; ms++)
        aoff[ms] = (uint32_t)(wm * 64 + ms * 16 + (lane & 15)) * PITCH
                 + (uint32_t)(lane >> 4) * 16;
#pragma unroll
    for (int np = 0; np < 4; np++)
        boff[np] = BH_OFF
                 + (uint32_t)(wn * 64 + np * 16 + (lane & 7) + ((lane >> 4) & 1) * 8)
                 * PITCH + (uint32_t)((lane >> 3) & 1) * 16;

    while (true) {
        if (tid == 0) sidx = atomicAdd(&g_next, 1);
        __syncthreads();
        const int idx = sidx;
        __syncthreads();                 // sidx consumed before next overwrite
        if (idx >= TOTAL_ITEMS) return;

        const bool G2 = idx >= G1_ITEMS;
        const int t  = G2 ? idx - G1_ITEMS : idx;
        const int e  = t / TILES_PER_E;
        const int mt = (t % TILES_PER_E) >> 3;
        const int nt = t & 7;
        const int m0 = mt * 256, n0 = nt * 128;
        const int loadE = g_load[e];

        if (G2) {                        // wait for this expert's gemm1 tiles
            if (tid == 0)
                while (ld_acq(&g_done[e]) < TILES_PER_E) __nanosleep(64);
            __syncthreads();
        }

        if (m0 < loadE) {
            size_t abase;
            if (G2) abase = ((size_t)e * CAP + m0 + tid) * DIM;
            else {
                int m = m0 + tid;
                abase = (size_t)g_row_token[e * CAP + (m < loadE ? m : loadE - 1)] * DIM;
            }
            const uint16_t* pA = (G2 ? g_Hh : g_xh) + abase;
            const uint16_t* pB = (G2 ? g_w2h : g_w1h)
                               + ((size_t)e * DIM + n0 + (tid & 127)) * DIM;
            const uint32_t dA = (uint32_t)tid * PITCH;
            const uint32_t dB = BH_OFF + (uint32_t)(tid & 127) * PITCH;

            auto issue = [&](int c, uint32_t st) {
                const int k0 = c * BK;
                const uint16_t* sa = pA + k0;
#pragma unroll
                for (int q = 0; q < 8; q++) cpa16(st + dA + q * 16, sa + q * 8);
                if (tid < 128) {
                    const uint16_t* sbp = pB + k0;
#pragma unroll
                    for (int q = 0; q < 8; q++) cpa16(st + dB + q * 16, sbp + q * 8);
                }
            };

            float acc[4][8][4];
#pragma unroll
            for (int i = 0; i < 4; i++)
#pragma unroll
                for (int j = 0; j < 8; j++)
#pragma unroll
                    for (int k = 0; k < 4; k++) acc[i][j][k] = 0.f;

            issue(0, st0);           CP_COMMIT();
            issue(1, st0 + STAGE_B); CP_COMMIT();

            int stg = 0;
#pragma unroll 1
            for (int c = 0; c < NCH; c++) {
                CP_WAIT1();
                __syncthreads();
                const uint32_t st = st0 + (uint32_t)stg * STAGE_B;
                uint32_t ah[2][16], bh[2][16];
#pragma unroll
                for (int ms = 0; ms < 4; ms++)
                    ldsm4(&ah[0][4 * ms], st + aoff[ms]);
#pragma unroll
                for (int np = 0; np < 4; np++)
                    ldsm4(&bh[0][4 * np], st + boff[np]);
#pragma unroll
                for (int s = 0; s < 4; s++) {       // 4 k16-steps per BK=64
                    const int cur = s & 1, nxt = cur ^ 1;
                    if (s < 3) {
#pragma unroll
                        for (int ms = 0; ms < 4; ms++)
                            ldsm4(&ah[nxt][4 * ms], st + aoff[ms] + (s + 1) * 32);
#pragma unroll
                        for (int np = 0; np < 4; np++)
                            ldsm4(&bh[nxt][4 * np], st + boff[np] + (s + 1) * 32);
                    }
#pragma unroll
                    for (int ms = 0; ms < 4; ms++)
#pragma unroll
                        for (int ns = 0; ns < 8; ns++)
                            mma_f16(acc[ms][ns], &ah[cur][4 * ms], &bh[cur][2 * ns]);
                }
                if (c + 2 < NCH) {
                    int nss = stg + 2; if (nss >= 3) nss -= 3;
                    issue(c + 2, st0 + (uint32_t)nss * STAGE_B);
                }
                CP_COMMIT();             // always commit (empty group ok)
                stg = (stg == 2) ? 0 : stg + 1;
            }

            // ---- epilogue ----
            const float* bE = (G2 ? b2 : b1) + e * DIM;
#pragma unroll
            for (int ms = 0; ms < 4; ms++) {
                const int row = m0 + wm * 64 + ms * 16 + (lane >> 2);
                float gr0 = 1.f, gr1 = 1.f;
                if (G2) {
                    gr0 = g_row_gate[e * CAP + row];
                    gr1 = g_row_gate[e * CAP + row + 8];
                }
#pragma unroll
                for (int ns = 0; ns < 8; ns++) {
                    const int col = n0 + wn * 64 + ns * 8 + 2 * (lane & 3);
                    const float2 bv = *(const float2*)(bE + col);
                    float2 v0, v1;
                    v0.x = acc[ms][ns][0] + bv.x; v0.y = acc[ms][ns][1] + bv.y;
                    v1.x = acc[ms][ns][2] + bv.x; v1.y = acc[ms][ns][3] + bv.y;
                    const size_t idx0 = ((size_t)e * CAP + row) * DIM + col;
                    if (G2) {
                        *(uint32_t*)(g_Oh + idx0) = cvt2h(v0.x * gr0, v0.y * gr0);
                        *(uint32_t*)(g_Oh + idx0 + 8 * DIM) = cvt2h(v1.x * gr1, v1.y * gr1);
                    } else {
                        v0.x = v0.x > 0.f ? v0.x : 0.f; v0.y = v0.y > 0.f ? v0.y : 0.f;
                        v1.x = v1.x > 0.f ? v1.x : 0.f; v1.y = v1.y > 0.f ? v1.y : 0.f;
                        *(uint32_t*)(g_Hh + idx0) = cvt2h(v0.x, v0.y);
                        *(uint32_t*)(g_Hh + idx0 + 8 * DIM) = cvt2h(v1.x, v1.y);
                    }
                }
            }
        }

        __syncthreads();                 // all stores done before release
        if (!G2 && tid == 0) {
            __threadfence();
            atomicAdd(&g_done[e], 1);
        }
    }
}

// ---------------- combine (+stats block): out[t] = sum_k Oh[e_k, slot_k] ---
__global__ void combine_kernel(float* __restrict__ out) {
    if (blockIdx.x == NTOK / 8) {        // stats block
        if (threadIdx.x == 0) {
            float l[NE], s = 0.f;
#pragma unroll
            for (int e = 0; e < NE; e++) { l[e] = (float)g_load[e]; s += l[e]; }
            float inv = 1.f / (s + 1e-8f);
            float loss = 0.f;
#pragma unroll
            for (int e = 0; e < NE; e++) {
                float d = l[e] * inv;
                out[(size_t)NTOK * DIM + 1 + e] = d;
                loss -= d * logf(d + 1e-8f);
            }
            out[(size_t)NTOK * DIM] = loss;
        }
        return;
    }
    int t = blockIdx.x * 8 + (threadIdx.x >> 5);
    int lane = threadIdx.x & 31;
    float acc[4][8];
#pragma unroll
    for (int i = 0; i < 4; i++)
#pragma unroll
        for (int j = 0; j < 8; j++) acc[i][j] = 0.f;
#pragma unroll
    for (int k = 0; k < 2; k++) {
        int s = g_slot[2 * t + k];
        if (s >= 0) {
            int e = g_top[2 * t + k];
            const uint4* p = (const uint4*)(g_Oh + ((size_t)e * CAP + s) * DIM);
#pragma unroll
            for (int i = 0; i < 4; i++) {
                uint4 v = __ldg(p + lane + i * 32);
                const uint32_t w[4] = {v.x, v.y, v.z, v.w};
#pragma unroll
                for (int j = 0; j < 4; j++) {
                    float2 f = __half22float2(*(const __half2*)&w[j]);
                    acc[i][2 * j]     += f.x;
                    acc[i][2 * j + 1] += f.y;
                }
            }
        }
    }
    float4* o = (float4*)(out + (size_t)t * DIM);
#pragma unroll
    for (int i = 0; i < 4; i++) {
        o[2 * (lane + i * 32)]     = make_float4(acc[i][0], acc[i][1], acc[i][2], acc[i][3]);
        o[2 * (lane + i * 32) + 1] = make_float4(acc[i][4], acc[i][5], acc[i][6], acc[i][7]);
    }
}

// ---------------- launch ----------------------------------------------------
extern "C" void kernel_launch(void* const* d_in, const int* in_sizes, int n_in,
                              void* d_out, int out_size) {
    const float* x  = (const float*)d_in[0];
    const float* Wr = (const float*)d_in[1];
    const float* br = (const float*)d_in[2];
    const float* W1 = (const float*)d_in[3];
    const float* b1 = (const float*)d_in[4];
    const float* W2 = (const float*)d_in[5];
    const float* b2 = (const float*)d_in[6];
    float* out = (float*)d_out;

    cudaFuncSetAttribute(moe_gemm_fused,
                         cudaFuncAttributeMaxDynamicSharedMemorySize, SMEM_DYN);

    void *pnext, *pdone;
    cudaGetSymbolAddress(&pnext, g_next);
    cudaGetSymbolAddress(&pdone, g_done);
    cudaMemsetAsync(pnext, 0, sizeof(int), 0);
    cudaMemsetAsync(pdone, 0, NE * sizeof(int), 0);

    prep_kernel<<<RBLK + WBLK, 256>>>(x, Wr, br, W1, W2);
    scan_kernel<<<NE, 1024>>>();
    moe_gemm_fused<<<GRID_PERSIST, 256, SMEM_DYN>>>(b1, b2);
    combine_kernel<<<NTOK / 8 + 1, 256>>>(out);
}

// round 13
// speedup vs baseline: 1.0138x; 1.0138x over previous
#include <cuda_runtime.h>
#include <cuda_fp16.h>
#include <cstdint>
#include <math.h>

#define NTOK 16384
#define DIM  1024
#define NE   8
#define CAP  2560          // int(1.25 * 16384 / 8)
#define BK   64
#define NCH  (DIM / BK)    // 16
#define PITCH 144          // 64 fp16 = 128B + 16B pad (conflict-free phases)
#define BH_OFF  36864      // 256*144 (A tile)
#define STAGE_B 55296      // A 36864 + B 18432
#define SMEM_DYN (1024 + 3 * STAGE_B)   // 166912
#define TILES_PER_E 80     // 10 m-tiles x 8 n-tiles
#define G1_ITEMS (NE * TILES_PER_E)     // 640
#define TOTAL_ITEMS (2 * G1_ITEMS)      // 1280
#define GRID_PERSIST 152
#define WN4  (NE * DIM * DIM / 4)       // float4 count per W tensor

// ---------------- device scratch (no allocation allowed) -------------------
__device__ int      g_top[NTOK * 2];
__device__ float    g_gate[NTOK * 2];
__device__ int      g_slot[NTOK * 2];
__device__ int      g_row_token[NE * CAP];
__device__ float    g_row_gate[NE * CAP];
__device__ int      g_load[NE];
__device__ int      g_next;                            // work-queue cursor
__device__ int      g_done[NE];                        // gemm1 tiles done / expert
__device__ uint16_t g_xh[(size_t)NTOK * DIM];          // x as fp16
__device__ uint16_t g_w1h[(size_t)NE * DIM * DIM];     // W1 as fp16
__device__ uint16_t g_w2h[(size_t)NE * DIM * DIM];     // W2 as fp16
__device__ uint16_t g_Hh[(size_t)NE * CAP * DIM];      // hidden as fp16
__device__ uint16_t g_Oh[(size_t)NE * CAP * DIM];      // gated expert out, fp16

// ---------------- helpers ---------------------------------------------------
__device__ __forceinline__ uint32_t smem_u32(const void* p) {
    uint32_t a;
    asm("{ .reg .u64 t; cvta.to.shared.u64 t, %1; cvt.u32.u64 %0, t; }"
        : "=r"(a) : "l"(p));
    return a;
}
__device__ __forceinline__ void cpa16(uint32_t dst, const void* src) {
    asm volatile("cp.async.cg.shared.global [%0], [%1], 16;"
                 :: "r"(dst), "l"(src));
}
#define CP_COMMIT() asm volatile("cp.async.commit_group;" ::: "memory")
#define CP_WAIT1()  asm volatile("cp.async.wait_group 1;" ::: "memory")

__device__ __forceinline__ void ldsm4(uint32_t* r, uint32_t addr) {
    asm volatile("ldmatrix.sync.aligned.m8n8.x4.shared.b16 {%0,%1,%2,%3}, [%4];"
                 : "=r"(r[0]), "=r"(r[1]), "=r"(r[2]), "=r"(r[3]) : "r"(addr));
}
__device__ __forceinline__ void mma_f16(float* d, const uint32_t* a,
                                        const uint32_t* b) {
    asm volatile(
        "mma.sync.aligned.m16n8k16.row.col.f32.f16.f16.f32 "
        "{%0,%1,%2,%3}, {%4,%5,%6,%7}, {%8,%9}, {%0,%1,%2,%3};"
        : "+f"(d[0]), "+f"(d[1]), "+f"(d[2]), "+f"(d[3])
        : "r"(a[0]), "r"(a[1]), "r"(a[2]), "r"(a[3]), "r"(b[0]), "r"(b[1]));
}
__device__ __forceinline__ uint32_t cvt2h(float a, float b) {
    __half2 h = __floats2half2_rn(a, b);
    return *(uint32_t*)&h;
}
__device__ __forceinline__ int ld_acq(const int* p) {
    int v;
    asm volatile("ld.acquire.gpu.global.b32 %0, [%1];" : "=r"(v) : "l"(p));
    return v;
}

// ---------------- W convert: fp32 -> fp16 (W1 and W2, one launch) ----------
__global__ void __launch_bounds__(256)
cvtw_kernel(const float4* __restrict__ W1, const float4* __restrict__ W2) {
    int i = blockIdx.x * 256 + threadIdx.x;
    const float4* src;
    uint2* dst;
    if (i < WN4) { src = W1; dst = (uint2*)g_w1h; }
    else         { src = W2; dst = (uint2*)g_w2h; i -= WN4; }
    float4 v = __ldg(src + i);
    dst[i] = make_uint2(cvt2h(v.x, v.y), cvt2h(v.z, v.w));
}

// ---------------- router + x->fp16, 4 tokens/warp --------------------------
__global__ void __launch_bounds__(256)
router_kernel(const float* __restrict__ x, const float* __restrict__ Wr,
              const float* __restrict__ br) {
    const int tid = threadIdx.x;
    const int lane = tid & 31, wid = tid >> 5;
    const int tb = (blockIdx.x * 8 + wid) * 4;
    const float4* xr[4];
    uint2* xo[4];
#pragma unroll
    for (int t = 0; t < 4; t++) {
        xr[t] = (const float4*)(x + (size_t)(tb + t) * DIM);
        xo[t] = (uint2*)(g_xh + (size_t)(tb + t) * DIM);
    }
    float acc[4][NE];
#pragma unroll
    for (int t = 0; t < 4; t++)
#pragma unroll
        for (int e = 0; e < NE; e++) acc[t][e] = 0.f;
#pragma unroll
    for (int i = 0; i < 8; i++) {
        const int d4 = lane + i * 32;
        float4 xv[4];
#pragma unroll
        for (int t = 0; t < 4; t++) {
            xv[t] = __ldg(xr[t] + d4);
            xo[t][d4] = make_uint2(cvt2h(xv[t].x, xv[t].y), cvt2h(xv[t].z, xv[t].w));
        }
#pragma unroll
        for (int e = 0; e < NE; e++) {
            const float4 w = __ldg((const float4*)(Wr + e * DIM) + d4);
#pragma unroll
            for (int t = 0; t < 4; t++)
                acc[t][e] += xv[t].x * w.x + xv[t].y * w.y
                           + xv[t].z * w.z + xv[t].w * w.w;
        }
    }
#pragma unroll
    for (int t = 0; t < 4; t++)
#pragma unroll
        for (int e = 0; e < NE; e++)
#pragma unroll
            for (int o = 16; o; o >>= 1)
                acc[t][e] += __shfl_xor_sync(0xffffffffu, acc[t][e], o);
    if (lane == 0) {
#pragma unroll
        for (int t = 0; t < 4; t++) {
            const int token = tb + t;
            float l[NE];
#pragma unroll
            for (int e = 0; e < NE; e++) l[e] = acc[t][e] + br[e];
            float v1 = -3.4e38f; int i1 = 0;
#pragma unroll
            for (int e = 0; e < NE; e++) if (l[e] > v1) { v1 = l[e]; i1 = e; }
            float v2 = -3.4e38f; int i2 = 0;
#pragma unroll
            for (int e = 0; e < NE; e++) if (e != i1 && l[e] > v2) { v2 = l[e]; i2 = e; }
            float ex = expf(v2 - v1);
            float inv = 1.f / (1.f + ex);
            g_top[2 * token]      = i1;
            g_top[2 * token + 1]  = i2;
            g_gate[2 * token]     = inv;
            g_gate[2 * token + 1] = ex * inv;
        }
    }
}

// ---------------- dispatch scan: 16 tokens/thread, one block scan ----------
__global__ void __launch_bounds__(1024)
scan_kernel() {
    const int e = blockIdx.x;
    const int tid = threadIdx.x;
    const int lane = tid & 31, wid = tid >> 5;
    __shared__ int wsum[32];
    __shared__ int stotal;

    const int base = tid * 16;
    unsigned mask = 0, which = 0;
    int cnt = 0;
#pragma unroll
    for (int j = 0; j < 16; j++) {
        const int n = base + j;
        const int t0 = g_top[2 * n], t1 = g_top[2 * n + 1];
        const bool m0 = (t0 == e), m1 = (t1 == e);
        if (m0 | m1) {
            mask |= 1u << j;
            if (!m0) which |= 1u << j;
            cnt++;
        }
    }
    int s = cnt;
#pragma unroll
    for (int o = 1; o < 32; o <<= 1) {
        int u = __shfl_up_sync(0xffffffffu, s, o);
        if (lane >= o) s += u;
    }
    if (lane == 31) wsum[wid] = s;
    const int wexcl = s - cnt;
    __syncthreads();
    if (wid == 0) {
        int v = wsum[lane];
        int ss = v;
#pragma unroll
        for (int o = 1; o < 32; o <<= 1) {
            int u = __shfl_up_sync(0xffffffffu, ss, o);
            if (lane >= o) ss += u;
        }
        wsum[lane] = ss - v;
        if (lane == 31) stotal = ss;
    }
    __syncthreads();
    int pos = wsum[wid] + wexcl;
#pragma unroll
    for (int j = 0; j < 16; j++) {
        if (mask & (1u << j)) {
            const int n = base + j;
            const int k = (which >> j) & 1;
            if (pos < CAP) {
                g_row_token[e * CAP + pos] = n;
                g_row_gate[e * CAP + pos]  = g_gate[2 * n + k];
                g_slot[2 * n + k] = pos;
            } else {
                g_slot[2 * n + k] = -1;
            }
            pos++;
        }
    }
    if (tid == 0) g_load[e] = stotal < CAP ? stotal : CAP;
}

// ---------------- fused persistent GEMM (both layers, work queue) ----------
__global__ void __launch_bounds__(256)
moe_gemm_fused(const float* __restrict__ b1, const float* __restrict__ b2) {
    extern __shared__ __align__(16) char dsm[];
    __shared__ int sidx;

    const int tid = threadIdx.x;
    const int lane = tid & 31, wid = tid >> 5;
    const int wm = wid >> 1, wn = wid & 1;     // warp tile 64x64
    const uint32_t sb = smem_u32(dsm);
    const uint32_t st0 = sb + 1024;

    uint32_t aoff[4], boff[4];
#pragma unroll
    for (int ms = 0; ms < 4; ms++)
        aoff[ms] = (uint32_t)(wm * 64 + ms * 16 + (lane & 15)) * PITCH
                 + (uint32_t)(lane >> 4) * 16;
#pragma unroll
    for (int np = 0; np < 4; np++)
        boff[np] = BH_OFF
                 + (uint32_t)(wn * 64 + np * 16 + (lane & 7) + ((lane >> 4) & 1) * 8)
                 * PITCH + (uint32_t)((lane >> 3) & 1) * 16;

    while (true) {
        if (tid == 0) sidx = atomicAdd(&g_next, 1);
        __syncthreads();
        const int idx = sidx;
        __syncthreads();                 // sidx consumed before next overwrite
        if (idx >= TOTAL_ITEMS) return;

        const bool G2 = idx >= G1_ITEMS;
        const int t  = G2 ? idx - G1_ITEMS : idx;
        const int e  = t / TILES_PER_E;
        const int mt = (t % TILES_PER_E) >> 3;
        const int nt = t & 7;
        const int m0 = mt * 256, n0 = nt * 128;
        const int loadE = g_load[e];

        if (G2) {                        // wait for this expert's gemm1 tiles
            if (tid == 0)
                while (ld_acq(&g_done[e]) < TILES_PER_E) __nanosleep(64);
            __syncthreads();
        }

        if (m0 < loadE) {
            size_t abase;
            if (G2) abase = ((size_t)e * CAP + m0 + tid) * DIM;
            else {
                int m = m0 + tid;
                abase = (size_t)g_row_token[e * CAP + (m < loadE ? m : loadE - 1)] * DIM;
            }
            const uint16_t* pA = (G2 ? g_Hh : g_xh) + abase;
            const uint16_t* pB = (G2 ? g_w2h : g_w1h)
                               + ((size_t)e * DIM + n0 + (tid & 127)) * DIM;
            const uint32_t dA = (uint32_t)tid * PITCH;
            const uint32_t dB = BH_OFF + (uint32_t)(tid & 127) * PITCH;

            auto issue = [&](int c, uint32_t st) {
                const int k0 = c * BK;
                const uint16_t* sa = pA + k0;
#pragma unroll
                for (int q = 0; q < 8; q++) cpa16(st + dA + q * 16, sa + q * 8);
                if (tid < 128) {
                    const uint16_t* sbp = pB + k0;
#pragma unroll
                    for (int q = 0; q < 8; q++) cpa16(st + dB + q * 16, sbp + q * 8);
                }
            };

            float acc[4][8][4];
#pragma unroll
            for (int i = 0; i < 4; i++)
#pragma unroll
                for (int j = 0; j < 8; j++)
#pragma unroll
                    for (int k = 0; k < 4; k++) acc[i][j][k] = 0.f;

            issue(0, st0);           CP_COMMIT();
            issue(1, st0 + STAGE_B); CP_COMMIT();

            int stg = 0;
#pragma unroll 1
            for (int c = 0; c < NCH; c++) {
                CP_WAIT1();
                __syncthreads();
                const uint32_t st = st0 + (uint32_t)stg * STAGE_B;
                uint32_t ah[2][16], bh[2][16];
#pragma unroll
                for (int ms = 0; ms < 4; ms++)
                    ldsm4(&ah[0][4 * ms], st + aoff[ms]);
#pragma unroll
                for (int np = 0; np < 4; np++)
                    ldsm4(&bh[0][4 * np], st + boff[np]);
#pragma unroll
                for (int s = 0; s < 4; s++) {       // 4 k16-steps per BK=64
                    const int cur = s & 1, nxt = cur ^ 1;
                    if (s < 3) {
#pragma unroll
                        for (int ms = 0; ms < 4; ms++)
                            ldsm4(&ah[nxt][4 * ms], st + aoff[ms] + (s + 1) * 32);
#pragma unroll
                        for (int np = 0; np < 4; np++)
                            ldsm4(&bh[nxt][4 * np], st + boff[np] + (s + 1) * 32);
                    }
#pragma unroll
                    for (int ms = 0; ms < 4; ms++)
#pragma unroll
                        for (int ns = 0; ns < 8; ns++)
                            mma_f16(acc[ms][ns], &ah[cur][4 * ms], &bh[cur][2 * ns]);
                }
                if (c + 2 < NCH) {
                    int nss = stg + 2; if (nss >= 3) nss -= 3;
                    issue(c + 2, st0 + (uint32_t)nss * STAGE_B);
                }
                CP_COMMIT();             // always commit (empty group ok)
                stg = (stg == 2) ? 0 : stg + 1;
            }

            // ---- epilogue ----
            const float* bE = (G2 ? b2 : b1) + e * DIM;
#pragma unroll
            for (int ms = 0; ms < 4; ms++) {
                const int row = m0 + wm * 64 + ms * 16 + (lane >> 2);
                float gr0 = 1.f, gr1 = 1.f;
                if (G2) {
                    gr0 = g_row_gate[e * CAP + row];
                    gr1 = g_row_gate[e * CAP + row + 8];
                }
#pragma unroll
                for (int ns = 0; ns < 8; ns++) {
                    const int col = n0 + wn * 64 + ns * 8 + 2 * (lane & 3);
                    const float2 bv = *(const float2*)(bE + col);
                    float2 v0, v1;
                    v0.x = acc[ms][ns][0] + bv.x; v0.y = acc[ms][ns][1] + bv.y;
                    v1.x = acc[ms][ns][2] + bv.x; v1.y = acc[ms][ns][3] + bv.y;
                    const size_t idx0 = ((size_t)e * CAP + row) * DIM + col;
                    if (G2) {
                        *(uint32_t*)(g_Oh + idx0) = cvt2h(v0.x * gr0, v0.y * gr0);
                        *(uint32_t*)(g_Oh + idx0 + 8 * DIM) = cvt2h(v1.x * gr1, v1.y * gr1);
                    } else {
                        v0.x = v0.x > 0.f ? v0.x : 0.f; v0.y = v0.y > 0.f ? v0.y : 0.f;
                        v1.x = v1.x > 0.f ? v1.x : 0.f; v1.y = v1.y > 0.f ? v1.y : 0.f;
                        *(uint32_t*)(g_Hh + idx0) = cvt2h(v0.x, v0.y);
                        *(uint32_t*)(g_Hh + idx0 + 8 * DIM) = cvt2h(v1.x, v1.y);
                    }
                }
            }
        }

        __syncthreads();                 // all stores done before release
        if (!G2 && tid == 0) {
            __threadfence();
            atomicAdd(&g_done[e], 1);
        }
    }
}

// ---------------- combine (+stats block): out[t] = sum_k Oh[e_k, slot_k] ---
__global__ void combine_kernel(float* __restrict__ out) {
    if (blockIdx.x == NTOK / 8) {        // stats block
        if (threadIdx.x == 0) {
            float l[NE], s = 0.f;
#pragma unroll
            for (int e = 0; e < NE; e++) { l[e] = (float)g_load[e]; s += l[e]; }
            float inv = 1.f / (s + 1e-8f);
            float loss = 0.f;
#pragma unroll
            for (int e = 0; e < NE; e++) {
                float d = l[e] * inv;
                out[(size_t)NTOK * DIM + 1 + e] = d;
                loss -= d * logf(d + 1e-8f);
            }
            out[(size_t)NTOK * DIM] = loss;
        }
        return;
    }
    int t = blockIdx.x * 8 + (threadIdx.x >> 5);
    int lane = threadIdx.x & 31;
    float acc[4][8];
#pragma unroll
    for (int i = 0; i < 4; i++)
#pragma unroll
        for (int j = 0; j < 8; j++) acc[i][j] = 0.f;
#pragma unroll
    for (int k = 0; k < 2; k++) {
        int s = g_slot[2 * t + k];
        if (s >= 0) {
            int e = g_top[2 * t + k];
            const uint4* p = (const uint4*)(g_Oh + ((size_t)e * CAP + s) * DIM);
#pragma unroll
            for (int i = 0; i < 4; i++) {
                uint4 v = __ldg(p + lane + i * 32);
                const uint32_t w[4] = {v.x, v.y, v.z, v.w};
#pragma unroll
                for (int j = 0; j < 4; j++) {
                    float2 f = __half22float2(*(const __half2*)&w[j]);
                    acc[i][2 * j]     += f.x;
                    acc[i][2 * j + 1] += f.y;
                }
            }
        }
    }
    float4* o = (float4*)(out + (size_t)t * DIM);
#pragma unroll
    for (int i = 0; i < 4; i++) {
        o[2 * (lane + i * 32)]     = make_float4(acc[i][0], acc[i][1], acc[i][2], acc[i][3]);
        o[2 * (lane + i * 32) + 1] = make_float4(acc[i][4], acc[i][5], acc[i][6], acc[i][7]);
    }
}

// ---------------- launch ----------------------------------------------------
extern "C" void kernel_launch(void* const* d_in, const int* in_sizes, int n_in,
                              void* d_out, int out_size) {
    const float* x  = (const float*)d_in[0];
    const float* Wr = (const float*)d_in[1];
    const float* br = (const float*)d_in[2];
    const float* W1 = (const float*)d_in[3];
    const float* b1 = (const float*)d_in[4];
    const float* W2 = (const float*)d_in[5];
    const float* b2 = (const float*)d_in[6];
    float* out = (float*)d_out;

    cudaFuncSetAttribute(moe_gemm_fused,
                         cudaFuncAttributeMaxDynamicSharedMemorySize, SMEM_DYN);

    void *pnext, *pdone;
    cudaGetSymbolAddress(&pnext, g_next);
    cudaGetSymbolAddress(&pdone, g_done);
    cudaMemsetAsync(pnext, 0, sizeof(int), 0);
    cudaMemsetAsync(pdone, 0, NE * sizeof(int), 0);

    cvtw_kernel<<<2 * WN4 / 256, 256>>>((const float4*)W1, (const float4*)W2);
    router_kernel<<<NTOK / 32, 256>>>(x, Wr, br);
    scan_kernel<<<NE, 1024>>>();
    moe_gemm_fused<<<GRID_PERSIST, 256, SMEM_DYN>>>(b1, b2);
    combine_kernel<<<NTOK / 8 + 1, 256>>>(out);
}